// round 2
// baseline (speedup 1.0000x reference)
#include <cuda_runtime.h>
#include <cuda_bf16.h>
#include <cstdint>

// Problem constants (match reference)
#define NTOK 16384
#define DIM  768
#define HID  768
#define COUT 2
#define NEXP 20

// GEMM1 tiling
#define BM 128
#define BN 128
#define BK 16

// -------- device scratch (no allocations allowed) --------
__device__ int   g_is64;                 // 1 if component_idx is int64, 0 if int32
__device__ int   g_counts[NEXP];
__device__ int   g_offsets[NEXP + 1];
__device__ int   g_cursor[NEXP];
__device__ int   g_sorted_idx[NTOK];     // original token id at sorted position
__device__ int   g_sorted_expert[NTOK];  // expert id at sorted position
__device__ float g_h[(size_t)NTOK * HID]; // hidden activations, sorted layout (~50MB)

// Decode expert id for token n under either dtype interpretation.
__device__ __forceinline__ int load_expert(const void* idx, int n) {
    if (g_is64) return (int)((const long long*)idx)[n];
    return ((const int*)idx)[n];
}

// -------- kernel 1a: zero counters, assume int64 until disproven --------
__global__ void k_zero() {
    int t = threadIdx.x;
    if (t < NEXP) g_counts[t] = 0;
    if (t == 0) g_is64 = 1;
}

// -------- kernel 1b: dtype detector --------
// Reads only the first NTOK int32 words: in-bounds for both int32[NTOK] (exact)
// and int64[NTOK] (first half). If data is int64 (little-endian, values 0..19),
// every odd int32 word is 0. If data is int32, odd words are random expert ids
// and some are nonzero.
__global__ void k_detect(const int* __restrict__ idx32) {
    int i = blockIdx.x * blockDim.x + threadIdx.x;
    if (i < NTOK) {
        if ((i & 1) && idx32[i] != 0) g_is64 = 0;
    }
}

// -------- kernel 1c: histogram over experts --------
__global__ void k_hist(const void* __restrict__ idx) {
    int n = blockIdx.x * blockDim.x + threadIdx.x;
    if (n < NTOK) atomicAdd(&g_counts[load_expert(idx, n)], 1);
}

// -------- kernel 1d: exclusive scan (E=20, single thread is fine) --------
__global__ void k_scan() {
    if (threadIdx.x == 0 && blockIdx.x == 0) {
        int off = 0;
        for (int e = 0; e < NEXP; e++) {
            g_offsets[e] = off;
            g_cursor[e]  = off;
            off += g_counts[e];
        }
        g_offsets[NEXP] = off;
    }
}

// -------- kernel 1e: scatter tokens into sorted-by-expert order --------
__global__ void k_scatter(const void* __restrict__ idx) {
    int n = blockIdx.x * blockDim.x + threadIdx.x;
    if (n < NTOK) {
        int e = load_expert(idx, n);
        int p = atomicAdd(&g_cursor[e], 1);
        g_sorted_idx[p]    = n;
        g_sorted_expert[p] = e;
    }
}

// -------- kernel 2: grouped GEMM1 + bias + ReLU --------
// h_sorted[s, :] = relu( X[tok(s), :] @ W1[e] + b1[e] )
// grid = (HID/BN, ceil(NTOK/BM), NEXP); blocks beyond an expert's segment exit.
__global__ __launch_bounds__(256) void k_gemm1(
    const float* __restrict__ X,
    const float* __restrict__ W1,
    const float* __restrict__ b1)
{
    const int e = blockIdx.z;
    const int seg_lo = g_offsets[e];
    const int cnt    = g_offsets[e + 1] - seg_lo;
    const int m0 = blockIdx.y * BM;
    if (m0 >= cnt) return;
    const int n0 = blockIdx.x * BN;
    const int tid = threadIdx.x;

    __shared__ float As[BK][BM];
    __shared__ float Bs[BK][BN];

    // A-load mapping: thread loads 8 consecutive K-values of one gathered row
    const int m_a = tid & 127;          // 0..127  (row within M tile)
    const int k_a = (tid >> 7) * 8;     // 0 or 8  (k offset)
    const bool row_valid = (m0 + m_a) < cnt;
    const int tok = row_valid ? g_sorted_idx[seg_lo + m0 + m_a] : 0;
    const float* Arow = X + (size_t)tok * DIM;

    // B-load mapping: thread loads float4 along N, two k-planes
    const int n_b = (tid & 31) * 4;     // 0..124
    const int k_b = tid >> 5;           // 0..7
    const float* Bbase = W1 + (size_t)e * DIM * HID + n0;

    const int ty = tid >> 4;   // 0..15  (m micro-tile)
    const int tx = tid & 15;   // 0..15  (n micro-tile)

    float acc[8][8];
    #pragma unroll
    for (int i = 0; i < 8; i++)
        #pragma unroll
        for (int j = 0; j < 8; j++) acc[i][j] = 0.f;

    for (int k0 = 0; k0 < DIM; k0 += BK) {
        float4 av0 = *(const float4*)(Arow + k0 + k_a);
        float4 av1 = *(const float4*)(Arow + k0 + k_a + 4);
        float4 bv0 = *(const float4*)(Bbase + (size_t)(k0 + k_b) * HID + n_b);
        float4 bv1 = *(const float4*)(Bbase + (size_t)(k0 + k_b + 8) * HID + n_b);

        __syncthreads();
        As[k_a + 0][m_a] = av0.x;  As[k_a + 1][m_a] = av0.y;
        As[k_a + 2][m_a] = av0.z;  As[k_a + 3][m_a] = av0.w;
        As[k_a + 4][m_a] = av1.x;  As[k_a + 5][m_a] = av1.y;
        As[k_a + 6][m_a] = av1.z;  As[k_a + 7][m_a] = av1.w;
        *(float4*)&Bs[k_b][n_b]     = bv0;
        *(float4*)&Bs[k_b + 8][n_b] = bv1;
        __syncthreads();

        #pragma unroll
        for (int k = 0; k < BK; k++) {
            float4 a0 = *(const float4*)&As[k][ty * 8];
            float4 a1 = *(const float4*)&As[k][ty * 8 + 4];
            float4 b0 = *(const float4*)&Bs[k][tx * 8];
            float4 b1v = *(const float4*)&Bs[k][tx * 8 + 4];
            float a[8] = {a0.x, a0.y, a0.z, a0.w, a1.x, a1.y, a1.z, a1.w};
            float b[8] = {b0.x, b0.y, b0.z, b0.w, b1v.x, b1v.y, b1v.z, b1v.w};
            #pragma unroll
            for (int i = 0; i < 8; i++)
                #pragma unroll
                for (int j = 0; j < 8; j++)
                    acc[i][j] = fmaf(a[i], b[j], acc[i][j]);
        }
    }

    // epilogue: bias + relu, store to sorted h buffer (vectorized)
    const float* b1e = b1 + e * HID + n0 + tx * 8;
    float bias[8];
    #pragma unroll
    for (int j = 0; j < 8; j++) bias[j] = b1e[j];

    #pragma unroll
    for (int i = 0; i < 8; i++) {
        int m = m0 + ty * 8 + i;
        if (m < cnt) {
            float* hp = g_h + (size_t)(seg_lo + m) * HID + n0 + tx * 8;
            float v[8];
            #pragma unroll
            for (int j = 0; j < 8; j++) v[j] = fmaxf(acc[i][j] + bias[j], 0.f);
            *(float4*)(hp)     = make_float4(v[0], v[1], v[2], v[3]);
            *(float4*)(hp + 4) = make_float4(v[4], v[5], v[6], v[7]);
        }
    }
}

// -------- kernel 3: out[tok] = h_sorted[s] @ W2[e] + b2[e], one warp per token --------
__global__ __launch_bounds__(256) void k_gemm2(
    const float* __restrict__ W2,
    const float* __restrict__ b2,
    float* __restrict__ out)
{
    int gwarp = (blockIdx.x * blockDim.x + threadIdx.x) >> 5;
    int lane  = threadIdx.x & 31;
    if (gwarp >= NTOK) return;
    int s   = gwarp;
    int e   = g_sorted_expert[s];
    int tok = g_sorted_idx[s];
    const float* hrow = g_h + (size_t)s * HID;
    const float* w2   = W2 + (size_t)e * HID * COUT;

    float a0 = 0.f, a1 = 0.f;
    #pragma unroll 4
    for (int i = lane; i < HID; i += 32) {
        float hv = hrow[i];
        float2 w = *(const float2*)(w2 + i * 2);
        a0 = fmaf(hv, w.x, a0);
        a1 = fmaf(hv, w.y, a1);
    }
    #pragma unroll
    for (int o = 16; o > 0; o >>= 1) {
        a0 += __shfl_xor_sync(0xFFFFFFFFu, a0, o);
        a1 += __shfl_xor_sync(0xFFFFFFFFu, a1, o);
    }
    if (lane == 0) {
        out[tok * 2 + 0] = a0 + b2[e * 2 + 0];
        out[tok * 2 + 1] = a1 + b2[e * 2 + 1];
    }
}

extern "C" void kernel_launch(void* const* d_in, const int* in_sizes, int n_in,
                              void* d_out, int out_size) {
    const float* X   = (const float*)d_in[0];      // [N, D]
    const void*  cid = d_in[1];                    // [N] int32 or int64
    const float* W1  = (const float*)d_in[2];      // [E, D, H]
    const float* b1  = (const float*)d_in[3];      // [E, H]
    const float* W2  = (const float*)d_in[4];      // [E, H, C]
    const float* b2  = (const float*)d_in[5];      // [E, C]
    float*       out = (float*)d_out;              // [N, C]

    k_zero<<<1, 32>>>();
    k_detect<<<(NTOK + 255) / 256, 256>>>((const int*)cid);
    k_hist<<<(NTOK + 255) / 256, 256>>>(cid);
    k_scan<<<1, 1>>>();
    k_scatter<<<(NTOK + 255) / 256, 256>>>(cid);

    dim3 grid1(HID / BN, (NTOK + BM - 1) / BM, NEXP);
    k_gemm1<<<grid1, 256>>>(X, W1, b1);

    k_gemm2<<<(NTOK * 32 + 255) / 256, 256>>>(W2, b2, out);
}